// round 2
// baseline (speedup 1.0000x reference)
#include <cuda_runtime.h>
#include <cuda_bf16.h>
#include <math.h>

// Problem constants
#define BATCH   2
#define SEQ     2048
#define HIDDEN  2048
#define NHEADS  16
#define NKV     4
#define HEADDIM 128
#define KVDIM   (NKV * HEADDIM)        // 512
#define ROWS    (BATCH * SEQ)          // 4096

// Scratch (device globals; allocation-free per harness rules)
__device__ float g_Q[(size_t)ROWS * HIDDEN];   // [b,s,h,d] flattened
__device__ float g_K[(size_t)ROWS * KVDIM];    // [b,s,kv,d]
__device__ float g_V[(size_t)ROWS * KVDIM];
__device__ float g_O[(size_t)ROWS * HIDDEN];   // attention output [b,s,h,d]

// ---------------------------------------------------------------------------
// Tiled SGEMM with bias: C[M,N] = A[M,K] @ W[K,N] + bias[N]
// Block 128x128, BK=16, 256 threads, 8x8 micro-tile.
// Double-buffered smem with register-staged global prefetch:
// one __syncthreads per k-tile, global-load latency overlapped with FFMA.
// ---------------------------------------------------------------------------
#define BM 128
#define BN 128
#define BK 16
#define APITCH 132   // padded pitch for transposed A tile (conflict mitigation)

__global__ __launch_bounds__(256)
void gemm_bias_kernel(const float* __restrict__ A, const float* __restrict__ W,
                      const float* __restrict__ bias, float* __restrict__ C,
                      int M, int N, int Kd)
{
    __shared__ float As[2][BK * APITCH];   // [k][m], padded
    __shared__ float Bs[2][BK * BN];       // [k][n]

    const int tid = threadIdx.x;
    const int tr  = tid >> 4;           // 0..15 -> row group
    const int tc  = tid & 15;           // 0..15 -> col group
    const int m0  = blockIdx.y * BM;
    const int n0  = blockIdx.x * BN;

    // Per-thread global-load coordinates (fixed across tiles)
    // A: 512 float4 per tile, 2 per thread
    const int a_row0 = (0 * 256 + tid) >> 2;          // 0..127
    const int a_c40  = (0 * 256 + tid) & 3;           // 0..3
    const int a_row1 = (1 * 256 + tid) >> 2;
    const int a_c41  = (1 * 256 + tid) & 3;
    // B: 512 float4 per tile, 2 per thread
    const int b_row0 = (0 * 256 + tid) >> 5;          // 0..15
    const int b_c40  = (0 * 256 + tid) & 31;          // 0..31
    const int b_row1 = (1 * 256 + tid) >> 5;
    const int b_c41  = (1 * 256 + tid) & 31;

    float acc[8][8];
#pragma unroll
    for (int i = 0; i < 8; ++i)
#pragma unroll
        for (int j = 0; j < 8; ++j) acc[i][j] = 0.f;

    const int ntiles = Kd / BK;

    // --- Preload tile 0 into buffer 0 ---
    {
        float4 av0 = *(const float4*)&A[(size_t)(m0 + a_row0) * Kd + 0 + a_c40 * 4];
        float4 av1 = *(const float4*)&A[(size_t)(m0 + a_row1) * Kd + 0 + a_c41 * 4];
        float4 bv0 = *(const float4*)&W[(size_t)(0 + b_row0) * N + n0 + b_c40 * 4];
        float4 bv1 = *(const float4*)&W[(size_t)(0 + b_row1) * N + n0 + b_c41 * 4];
        As[0][(a_c40 * 4 + 0) * APITCH + a_row0] = av0.x;
        As[0][(a_c40 * 4 + 1) * APITCH + a_row0] = av0.y;
        As[0][(a_c40 * 4 + 2) * APITCH + a_row0] = av0.z;
        As[0][(a_c40 * 4 + 3) * APITCH + a_row0] = av0.w;
        As[0][(a_c41 * 4 + 0) * APITCH + a_row1] = av1.x;
        As[0][(a_c41 * 4 + 1) * APITCH + a_row1] = av1.y;
        As[0][(a_c41 * 4 + 2) * APITCH + a_row1] = av1.z;
        As[0][(a_c41 * 4 + 3) * APITCH + a_row1] = av1.w;
        *(float4*)&Bs[0][b_row0 * BN + b_c40 * 4] = bv0;
        *(float4*)&Bs[0][b_row1 * BN + b_c41 * 4] = bv1;
    }
    __syncthreads();

    for (int t = 0; t < ntiles; ++t) {
        const int buf = t & 1;
        float4 pa0, pa1, pb0, pb1;
        const bool has_next = (t + 1 < ntiles);
        if (has_next) {
            const int kt = (t + 1) * BK;
            pa0 = *(const float4*)&A[(size_t)(m0 + a_row0) * Kd + kt + a_c40 * 4];
            pa1 = *(const float4*)&A[(size_t)(m0 + a_row1) * Kd + kt + a_c41 * 4];
            pb0 = *(const float4*)&W[(size_t)(kt + b_row0) * N + n0 + b_c40 * 4];
            pb1 = *(const float4*)&W[(size_t)(kt + b_row1) * N + n0 + b_c41 * 4];
        }

#pragma unroll
        for (int k = 0; k < BK; ++k) {
            float4 a0 = *(float4*)&As[buf][k * APITCH + tr * 8];
            float4 a1 = *(float4*)&As[buf][k * APITCH + tr * 8 + 4];
            float4 b0 = *(float4*)&Bs[buf][k * BN + tc * 8];
            float4 b1 = *(float4*)&Bs[buf][k * BN + tc * 8 + 4];
            float av[8] = {a0.x, a0.y, a0.z, a0.w, a1.x, a1.y, a1.z, a1.w};
            float bv[8] = {b0.x, b0.y, b0.z, b0.w, b1.x, b1.y, b1.z, b1.w};
#pragma unroll
            for (int i = 0; i < 8; ++i)
#pragma unroll
                for (int j = 0; j < 8; ++j)
                    acc[i][j] += av[i] * bv[j];
        }

        if (has_next) {
            const int nbuf = buf ^ 1;
            As[nbuf][(a_c40 * 4 + 0) * APITCH + a_row0] = pa0.x;
            As[nbuf][(a_c40 * 4 + 1) * APITCH + a_row0] = pa0.y;
            As[nbuf][(a_c40 * 4 + 2) * APITCH + a_row0] = pa0.z;
            As[nbuf][(a_c40 * 4 + 3) * APITCH + a_row0] = pa0.w;
            As[nbuf][(a_c41 * 4 + 0) * APITCH + a_row1] = pa1.x;
            As[nbuf][(a_c41 * 4 + 1) * APITCH + a_row1] = pa1.y;
            As[nbuf][(a_c41 * 4 + 2) * APITCH + a_row1] = pa1.z;
            As[nbuf][(a_c41 * 4 + 3) * APITCH + a_row1] = pa1.w;
            *(float4*)&Bs[nbuf][b_row0 * BN + b_c40 * 4] = pb0;
            *(float4*)&Bs[nbuf][b_row1 * BN + b_c41 * 4] = pb1;
            __syncthreads();
        }
    }

    // Epilogue with bias
    float4 bi0 = *(const float4*)&bias[n0 + tc * 8];
    float4 bi1 = *(const float4*)&bias[n0 + tc * 8 + 4];
#pragma unroll
    for (int i = 0; i < 8; ++i) {
        int row = m0 + tr * 8 + i;
        float4 c0 = make_float4(acc[i][0] + bi0.x, acc[i][1] + bi0.y,
                                acc[i][2] + bi0.z, acc[i][3] + bi0.w);
        float4 c1 = make_float4(acc[i][4] + bi1.x, acc[i][5] + bi1.y,
                                acc[i][6] + bi1.z, acc[i][7] + bi1.w);
        *(float4*)&C[(size_t)row * N + n0 + tc * 8]     = c0;
        *(float4*)&C[(size_t)row * N + n0 + tc * 8 + 4] = c1;
    }
}

// ---------------------------------------------------------------------------
// Flash attention (fp32, online softmax).
// Grid: (S/64, NHEADS, BATCH). Block: 256 threads.
// Q tile 64 rows; KV tiles of 64; d = 128.
// ---------------------------------------------------------------------------
#define QT 64
#define KT 64
#define QP 68    // padded pitch for transposed Q/K tiles ([d][row])

// dyn smem floats: Qst(128*68) + Kst(128*68) + Vs(64*128) + Ss(64*64) + 3*64
#define ATTN_SMEM_FLOATS (HEADDIM*QP*2 + KT*HEADDIM + QT*KT + 3*QT)
#define ATTN_SMEM_BYTES  (ATTN_SMEM_FLOATS * 4)

__global__ __launch_bounds__(256)
void attn_kernel(const float* __restrict__ Q, const float* __restrict__ K,
                 const float* __restrict__ V, float* __restrict__ O)
{
    extern __shared__ float sm[];
    float* Qst   = sm;                         // [d][row] pitch QP
    float* Kst   = Qst + HEADDIM * QP;         // [d][row] pitch QP
    float* Vs    = Kst + HEADDIM * QP;         // [row][d]
    float* Ss    = Vs + KT * HEADDIM;          // [qrow][krow]
    float* rowm  = Ss + QT * KT;
    float* rowl  = rowm + QT;
    float* rowsc = rowl + QT;

    const int qt  = blockIdx.x;
    const int h   = blockIdx.y;
    const int b   = blockIdx.z;
    const int kvh = h / (NHEADS / NKV);
    const int tid = threadIdx.x;
    const int q0  = qt * QT;
    const float scale = 0.08838834764831845f;  // 1/sqrt(128)

    // Load Q tile transposed, pre-scaled. (scalar loads, coalesced; stores 4-way)
    {
        const float* qbase = Q + ((size_t)(b * SEQ + q0)) * HIDDEN + h * HEADDIM;
#pragma unroll
        for (int i = 0; i < (QT * HEADDIM) / 256; ++i) {
            int idx = i * 256 + tid;
            int r = idx >> 7;
            int d = idx & 127;
            Qst[d * QP + r] = qbase[(size_t)r * HIDDEN + d] * scale;
        }
    }
    if (tid < QT) { rowm[tid] = -1e30f; rowl[tid] = 0.f; }

    const int ty = tid >> 4;   // 0..15
    const int tx = tid & 15;   // 0..15

    float acc[4][8];
#pragma unroll
    for (int i = 0; i < 4; ++i)
#pragma unroll
        for (int j = 0; j < 8; ++j) acc[i][j] = 0.f;

    for (int jt = 0; jt < SEQ / KT; ++jt) {
        __syncthreads();   // protect smem reuse across iterations

        // Load K tile transposed
        const float* kbase = K + ((size_t)(b * SEQ + jt * KT)) * KVDIM + kvh * HEADDIM;
#pragma unroll
        for (int i = 0; i < (KT * HEADDIM) / 256; ++i) {
            int idx = i * 256 + tid;
            int r = idx >> 7;
            int d = idx & 127;
            Kst[d * QP + r] = kbase[(size_t)r * KVDIM + d];
        }
        // Load V tile natural layout
        const float* vbase = V + ((size_t)(b * SEQ + jt * KT)) * KVDIM + kvh * HEADDIM;
#pragma unroll
        for (int i = 0; i < (KT * HEADDIM) / (256 * 4); ++i) {
            int idx4 = i * 256 + tid;
            int r  = idx4 >> 5;
            int c4 = idx4 & 31;
            *(float4*)&Vs[r * HEADDIM + c4 * 4] =
                *(const float4*)&vbase[(size_t)r * KVDIM + c4 * 4];
        }
        __syncthreads();

        // Scores: S = (Q*scale) @ K^T   (64x64, 4x4 per thread)
        float sacc[4][4];
#pragma unroll
        for (int i = 0; i < 4; ++i)
#pragma unroll
            for (int j = 0; j < 4; ++j) sacc[i][j] = 0.f;

#pragma unroll 8
        for (int kk = 0; kk < HEADDIM; ++kk) {
            float4 qv4 = *(float4*)&Qst[kk * QP + ty * 4];
            float4 kv4 = *(float4*)&Kst[kk * QP + tx * 4];
            float qv[4] = {qv4.x, qv4.y, qv4.z, qv4.w};
            float kv[4] = {kv4.x, kv4.y, kv4.z, kv4.w};
#pragma unroll
            for (int i = 0; i < 4; ++i)
#pragma unroll
                for (int j = 0; j < 4; ++j)
                    sacc[i][j] += qv[i] * kv[j];
        }
#pragma unroll
        for (int i = 0; i < 4; ++i) {
            *(float4*)&Ss[(ty * 4 + i) * KT + tx * 4] =
                make_float4(sacc[i][0], sacc[i][1], sacc[i][2], sacc[i][3]);
        }
        __syncthreads();

        // Online softmax: 4 threads per row (quad within warp)
        {
            int row = tid >> 2;
            int sub = tid & 3;
            float vals[16];
            float m_t = -1e30f;
#pragma unroll
            for (int k2 = 0; k2 < 16; ++k2) {
                vals[k2] = Ss[row * KT + sub + 4 * k2];
                m_t = fmaxf(m_t, vals[k2]);
            }
            m_t = fmaxf(m_t, __shfl_xor_sync(0xffffffffu, m_t, 1));
            m_t = fmaxf(m_t, __shfl_xor_sync(0xffffffffu, m_t, 2));
            float m_old = rowm[row];
            float m_new = fmaxf(m_old, m_t);
            float lsum = 0.f;
#pragma unroll
            for (int k2 = 0; k2 < 16; ++k2) {
                float p = __expf(vals[k2] - m_new);
                lsum += p;
                Ss[row * KT + sub + 4 * k2] = p;
            }
            lsum += __shfl_xor_sync(0xffffffffu, lsum, 1);
            lsum += __shfl_xor_sync(0xffffffffu, lsum, 2);
            if (sub == 0) {
                float sc = __expf(m_old - m_new);
                rowsc[row] = sc;
                rowl[row]  = rowl[row] * sc + lsum;
                rowm[row]  = m_new;
            }
        }
        __syncthreads();

        // Rescale accumulators and accumulate P @ V (rows ty*4.., cols tx*8..)
#pragma unroll
        for (int i = 0; i < 4; ++i) {
            float sc = rowsc[ty * 4 + i];
#pragma unroll
            for (int j = 0; j < 8; ++j) acc[i][j] *= sc;
        }
#pragma unroll 4
        for (int jj = 0; jj < KT; ++jj) {
            float4 v0 = *(float4*)&Vs[jj * HEADDIM + tx * 8];
            float4 v1 = *(float4*)&Vs[jj * HEADDIM + tx * 8 + 4];
#pragma unroll
            for (int i = 0; i < 4; ++i) {
                float p = Ss[(ty * 4 + i) * KT + jj];
                acc[i][0] += p * v0.x;
                acc[i][1] += p * v0.y;
                acc[i][2] += p * v0.z;
                acc[i][3] += p * v0.w;
                acc[i][4] += p * v1.x;
                acc[i][5] += p * v1.y;
                acc[i][6] += p * v1.z;
                acc[i][7] += p * v1.w;
            }
        }
    }

    // Epilogue: normalize by row sums, write O[b,s,h,d]
    float* obase = O + ((size_t)(b * SEQ + q0)) * HIDDEN + h * HEADDIM;
#pragma unroll
    for (int i = 0; i < 4; ++i) {
        int r = ty * 4 + i;
        float inv = 1.f / rowl[r];
        float4 o0 = make_float4(acc[i][0] * inv, acc[i][1] * inv,
                                acc[i][2] * inv, acc[i][3] * inv);
        float4 o1 = make_float4(acc[i][4] * inv, acc[i][5] * inv,
                                acc[i][6] * inv, acc[i][7] * inv);
        *(float4*)&obase[(size_t)r * HIDDEN + tx * 8]     = o0;
        *(float4*)&obase[(size_t)r * HIDDEN + tx * 8 + 4] = o1;
    }
}

// ---------------------------------------------------------------------------
// Launcher
// ---------------------------------------------------------------------------
extern "C" void kernel_launch(void* const* d_in, const int* in_sizes, int n_in,
                              void* d_out, int out_size)
{
    const float* x  = (const float*)d_in[0];
    const float* wq = (const float*)d_in[1];
    const float* bq = (const float*)d_in[2];
    const float* wk = (const float*)d_in[3];
    const float* bk = (const float*)d_in[4];
    const float* wv = (const float*)d_in[5];
    const float* bv = (const float*)d_in[6];
    const float* wo = (const float*)d_in[7];
    const float* bo = (const float*)d_in[8];
    float* out = (float*)d_out;

    float *Qp, *Kp, *Vp, *Op;
    cudaGetSymbolAddress((void**)&Qp, g_Q);
    cudaGetSymbolAddress((void**)&Kp, g_K);
    cudaGetSymbolAddress((void**)&Vp, g_V);
    cudaGetSymbolAddress((void**)&Op, g_O);

    cudaFuncSetAttribute(attn_kernel,
                         cudaFuncAttributeMaxDynamicSharedMemorySize,
                         ATTN_SMEM_BYTES);

    // Projections
    {
        dim3 gq(HIDDEN / BN, ROWS / BM);
        gemm_bias_kernel<<<gq, 256>>>(x, wq, bq, Qp, ROWS, HIDDEN, HIDDEN);
        dim3 gk(KVDIM / BN, ROWS / BM);
        gemm_bias_kernel<<<gk, 256>>>(x, wk, bk, Kp, ROWS, KVDIM, HIDDEN);
        gemm_bias_kernel<<<gk, 256>>>(x, wv, bv, Vp, ROWS, KVDIM, HIDDEN);
    }

    // Attention
    {
        dim3 ga(SEQ / QT, NHEADS, BATCH);
        attn_kernel<<<ga, 256, ATTN_SMEM_BYTES>>>(Qp, Kp, Vp, Op);
    }

    // Output projection
    {
        dim3 go(HIDDEN / BN, ROWS / BM);
        gemm_bias_kernel<<<go, 256>>>(Op, wo, bo, out, ROWS, HIDDEN, HIDDEN);
    }
}

// round 4
// speedup vs baseline: 1.5903x; 1.5903x over previous
#include <cuda_runtime.h>
#include <cuda_bf16.h>
#include <stdint.h>
#include <math.h>

// Problem constants
#define BATCH   2
#define SEQ     2048
#define HIDDEN  2048
#define NHEADS  16
#define NKV     4
#define HEADDIM 128
#define KVDIM   (NKV * HEADDIM)        // 512
#define ROWS    (BATCH * SEQ)          // 4096

// Scratch (device globals; allocation-free per harness rules)
__device__ float g_Q[(size_t)ROWS * HIDDEN];   // [b,s,h,d] flattened
__device__ float g_K[(size_t)ROWS * KVDIM];    // [b,s,kv,d]
__device__ float g_V[(size_t)ROWS * KVDIM];
__device__ float g_O[(size_t)ROWS * HIDDEN];   // attention output [b,s,h,d]

// ---------------------------------------------------------------------------
// TF32 tensor-core GEMM with bias: C[M,N] = A[M,K] @ W[K,N] + bias[N]
// mma.sync.m16n8k8.tf32, 128x128x32 CTA tile, 8 warps (4m x 2n), warp tile
// 32x64. cp.async double-buffered smem. Conflict-free fragment pitches.
// ---------------------------------------------------------------------------
#define TBM 128
#define TBN 128
#define TBK 32
#define APITCH 36     // (4g+t)%32 distinct for g<8,t<4  -> conflict-free A frags
#define BPITCH 136    // (8t+g)%32 distinct               -> conflict-free B frags

#define GEMM_SMEM_FLOATS (2 * TBM * APITCH + 2 * TBK * BPITCH)
#define GEMM_SMEM_BYTES  (GEMM_SMEM_FLOATS * 4)

__device__ __forceinline__ unsigned tf32cvt(float x) {
    unsigned r;
    asm("cvt.rna.tf32.f32 %0, %1;" : "=r"(r) : "f"(x));
    return r;
}

__device__ __forceinline__ void cpasync16(unsigned saddr, const void* g) {
    asm volatile("cp.async.cg.shared.global [%0], [%1], 16;" :: "r"(saddr), "l"(g));
}

__device__ __forceinline__ void mma_tf32(float c[4], const unsigned a[4],
                                         unsigned b0, unsigned b1) {
    asm volatile(
        "mma.sync.aligned.m16n8k8.row.col.f32.tf32.tf32.f32 "
        "{%0,%1,%2,%3}, {%4,%5,%6,%7}, {%8,%9}, {%0,%1,%2,%3};"
        : "+f"(c[0]), "+f"(c[1]), "+f"(c[2]), "+f"(c[3])
        : "r"(a[0]), "r"(a[1]), "r"(a[2]), "r"(a[3]), "r"(b0), "r"(b1));
}

__global__ __launch_bounds__(256)
void gemm_tf32_kernel(const float* __restrict__ A, const float* __restrict__ W,
                      const float* __restrict__ bias, float* __restrict__ C,
                      int M, int N, int Kd)
{
    extern __shared__ float sm[];
    float* AsBase = sm;                              // [2][TBM][APITCH]
    float* BsBase = sm + 2 * TBM * APITCH;           // [2][TBK][BPITCH]

    const int tid  = threadIdx.x;
    const int wid  = tid >> 5;
    const int lane = tid & 31;
    const int g    = lane >> 2;     // 0..7
    const int t    = lane & 3;      // 0..3
    const int warp_m = (wid & 3) * 32;   // 4 warps along M
    const int warp_n = (wid >> 2) * 64;  // 2 warps along N
    const int m0 = blockIdx.y * TBM;
    const int n0 = blockIdx.x * TBN;

    const unsigned smbase  = (unsigned)__cvta_generic_to_shared(sm);
    const unsigned asBaseU = smbase;
    const unsigned bsBaseU = smbase + 2u * TBM * APITCH * 4u;

    // Per-thread staging coords (4 float4 each for A and B)
    int a_row[4], a_c4[4], b_row[4], b_c4[4];
#pragma unroll
    for (int p = 0; p < 4; ++p) {
        int idx = p * 256 + tid;
        a_row[p] = idx >> 3;  a_c4[p] = idx & 7;    // A: 128 rows x 8 float4
        b_row[p] = idx >> 5;  b_c4[p] = idx & 31;   // B: 32 rows x 32 float4
    }

    float acc[2][8][4];
#pragma unroll
    for (int mf = 0; mf < 2; ++mf)
#pragma unroll
        for (int nf = 0; nf < 8; ++nf)
#pragma unroll
            for (int i = 0; i < 4; ++i) acc[mf][nf][i] = 0.f;

    const int ntiles = Kd / TBK;

    // Preload tile 0 into buffer 0
    {
#pragma unroll
        for (int p = 0; p < 4; ++p) {
            cpasync16(asBaseU + (unsigned)(a_row[p] * APITCH + a_c4[p] * 4) * 4u,
                      &A[(size_t)(m0 + a_row[p]) * Kd + 0 + a_c4[p] * 4]);
            cpasync16(bsBaseU + (unsigned)(b_row[p] * BPITCH + b_c4[p] * 4) * 4u,
                      &W[(size_t)(0 + b_row[p]) * N + n0 + b_c4[p] * 4]);
        }
        asm volatile("cp.async.commit_group;");
        asm volatile("cp.async.wait_group 0;");
    }
    __syncthreads();

    for (int tt = 0; tt < ntiles; ++tt) {
        const int buf  = tt & 1;
        const bool has_next = (tt + 1 < ntiles);

        if (has_next) {
            const int kt = (tt + 1) * TBK;
            const int nbuf = buf ^ 1;
            const unsigned asOff = asBaseU + (unsigned)nbuf * (TBM * APITCH * 4u);
            const unsigned bsOff = bsBaseU + (unsigned)nbuf * (TBK * BPITCH * 4u);
#pragma unroll
            for (int p = 0; p < 4; ++p) {
                cpasync16(asOff + (unsigned)(a_row[p] * APITCH + a_c4[p] * 4) * 4u,
                          &A[(size_t)(m0 + a_row[p]) * Kd + kt + a_c4[p] * 4]);
                cpasync16(bsOff + (unsigned)(b_row[p] * BPITCH + b_c4[p] * 4) * 4u,
                          &W[(size_t)(kt + b_row[p]) * N + n0 + b_c4[p] * 4]);
            }
            asm volatile("cp.async.commit_group;");
        }

        const float* As = AsBase + buf * (TBM * APITCH);
        const float* Bs = BsBase + buf * (TBK * BPITCH);

#pragma unroll
        for (int kk = 0; kk < 4; ++kk) {
            const int ks = kk * 8;
            unsigned afr[2][4];
#pragma unroll
            for (int mf = 0; mf < 2; ++mf) {
                const int rbase = warp_m + mf * 16;
                afr[mf][0] = tf32cvt(As[(rbase + g)     * APITCH + ks + t]);
                afr[mf][1] = tf32cvt(As[(rbase + g + 8) * APITCH + ks + t]);
                afr[mf][2] = tf32cvt(As[(rbase + g)     * APITCH + ks + t + 4]);
                afr[mf][3] = tf32cvt(As[(rbase + g + 8) * APITCH + ks + t + 4]);
            }
#pragma unroll
            for (int nf = 0; nf < 8; ++nf) {
                const int col = warp_n + nf * 8 + g;
                unsigned b0 = tf32cvt(Bs[(ks + t)     * BPITCH + col]);
                unsigned b1 = tf32cvt(Bs[(ks + t + 4) * BPITCH + col]);
                mma_tf32(acc[0][nf], afr[0], b0, b1);
                mma_tf32(acc[1][nf], afr[1], b0, b1);
            }
        }

        if (has_next) {
            asm volatile("cp.async.wait_group 0;");
            __syncthreads();
        }
    }

    // Epilogue with bias. c-frag: rows g / g+8, cols t*2 / t*2+1
#pragma unroll
    for (int mf = 0; mf < 2; ++mf) {
        const int r0 = m0 + warp_m + mf * 16 + g;
        const int r1 = r0 + 8;
#pragma unroll
        for (int nf = 0; nf < 8; ++nf) {
            const int col = n0 + warp_n + nf * 8 + t * 2;
            const float b0 = bias[col];
            const float b1 = bias[col + 1];
            float2 v0 = make_float2(acc[mf][nf][0] + b0, acc[mf][nf][1] + b1);
            float2 v1 = make_float2(acc[mf][nf][2] + b0, acc[mf][nf][3] + b1);
            *(float2*)&C[(size_t)r0 * N + col] = v0;
            *(float2*)&C[(size_t)r1 * N + col] = v1;
        }
    }
}

// ---------------------------------------------------------------------------
// Flash attention (fp32, online softmax). UNCHANGED from round-2 passing run.
// Grid: (S/64, NHEADS, BATCH). Block: 256 threads.
// ---------------------------------------------------------------------------
#define QT 64
#define KT 64
#define QP 68    // padded pitch for transposed Q/K tiles ([d][row])

#define ATTN_SMEM_FLOATS (HEADDIM*QP*2 + KT*HEADDIM + QT*KT + 3*QT)
#define ATTN_SMEM_BYTES  (ATTN_SMEM_FLOATS * 4)

__global__ __launch_bounds__(256)
void attn_kernel(const float* __restrict__ Q, const float* __restrict__ K,
                 const float* __restrict__ V, float* __restrict__ O)
{
    extern __shared__ float sm[];
    float* Qst   = sm;                         // [d][row] pitch QP
    float* Kst   = Qst + HEADDIM * QP;         // [d][row] pitch QP
    float* Vs    = Kst + HEADDIM * QP;         // [row][d]
    float* Ss    = Vs + KT * HEADDIM;          // [qrow][krow]
    float* rowm  = Ss + QT * KT;
    float* rowl  = rowm + QT;
    float* rowsc = rowl + QT;

    const int qt  = blockIdx.x;
    const int h   = blockIdx.y;
    const int b   = blockIdx.z;
    const int kvh = h / (NHEADS / NKV);
    const int tid = threadIdx.x;
    const int q0  = qt * QT;
    const float scale = 0.08838834764831845f;  // 1/sqrt(128)

    {
        const float* qbase = Q + ((size_t)(b * SEQ + q0)) * HIDDEN + h * HEADDIM;
#pragma unroll
        for (int i = 0; i < (QT * HEADDIM) / 256; ++i) {
            int idx = i * 256 + tid;
            int r = idx >> 7;
            int d = idx & 127;
            Qst[d * QP + r] = qbase[(size_t)r * HIDDEN + d] * scale;
        }
    }
    if (tid < QT) { rowm[tid] = -1e30f; rowl[tid] = 0.f; }

    const int ty = tid >> 4;   // 0..15
    const int tx = tid & 15;   // 0..15

    float acc[4][8];
#pragma unroll
    for (int i = 0; i < 4; ++i)
#pragma unroll
        for (int j = 0; j < 8; ++j) acc[i][j] = 0.f;

    for (int jt = 0; jt < SEQ / KT; ++jt) {
        __syncthreads();

        const float* kbase = K + ((size_t)(b * SEQ + jt * KT)) * KVDIM + kvh * HEADDIM;
#pragma unroll
        for (int i = 0; i < (KT * HEADDIM) / 256; ++i) {
            int idx = i * 256 + tid;
            int r = idx >> 7;
            int d = idx & 127;
            Kst[d * QP + r] = kbase[(size_t)r * KVDIM + d];
        }
        const float* vbase = V + ((size_t)(b * SEQ + jt * KT)) * KVDIM + kvh * HEADDIM;
#pragma unroll
        for (int i = 0; i < (KT * HEADDIM) / (256 * 4); ++i) {
            int idx4 = i * 256 + tid;
            int r  = idx4 >> 5;
            int c4 = idx4 & 31;
            *(float4*)&Vs[r * HEADDIM + c4 * 4] =
                *(const float4*)&vbase[(size_t)r * KVDIM + c4 * 4];
        }
        __syncthreads();

        float sacc[4][4];
#pragma unroll
        for (int i = 0; i < 4; ++i)
#pragma unroll
            for (int j = 0; j < 4; ++j) sacc[i][j] = 0.f;

#pragma unroll 8
        for (int kk = 0; kk < HEADDIM; ++kk) {
            float4 qv4 = *(float4*)&Qst[kk * QP + ty * 4];
            float4 kv4 = *(float4*)&Kst[kk * QP + tx * 4];
            float qv[4] = {qv4.x, qv4.y, qv4.z, qv4.w};
            float kv[4] = {kv4.x, kv4.y, kv4.z, kv4.w};
#pragma unroll
            for (int i = 0; i < 4; ++i)
#pragma unroll
                for (int j = 0; j < 4; ++j)
                    sacc[i][j] += qv[i] * kv[j];
        }
#pragma unroll
        for (int i = 0; i < 4; ++i) {
            *(float4*)&Ss[(ty * 4 + i) * KT + tx * 4] =
                make_float4(sacc[i][0], sacc[i][1], sacc[i][2], sacc[i][3]);
        }
        __syncthreads();

        {
            int row = tid >> 2;
            int sub = tid & 3;
            float vals[16];
            float m_t = -1e30f;
#pragma unroll
            for (int k2 = 0; k2 < 16; ++k2) {
                vals[k2] = Ss[row * KT + sub + 4 * k2];
                m_t = fmaxf(m_t, vals[k2]);
            }
            m_t = fmaxf(m_t, __shfl_xor_sync(0xffffffffu, m_t, 1));
            m_t = fmaxf(m_t, __shfl_xor_sync(0xffffffffu, m_t, 2));
            float m_old = rowm[row];
            float m_new = fmaxf(m_old, m_t);
            float lsum = 0.f;
#pragma unroll
            for (int k2 = 0; k2 < 16; ++k2) {
                float p = __expf(vals[k2] - m_new);
                lsum += p;
                Ss[row * KT + sub + 4 * k2] = p;
            }
            lsum += __shfl_xor_sync(0xffffffffu, lsum, 1);
            lsum += __shfl_xor_sync(0xffffffffu, lsum, 2);
            if (sub == 0) {
                float sc = __expf(m_old - m_new);
                rowsc[row] = sc;
                rowl[row]  = rowl[row] * sc + lsum;
                rowm[row]  = m_new;
            }
        }
        __syncthreads();

#pragma unroll
        for (int i = 0; i < 4; ++i) {
            float sc = rowsc[ty * 4 + i];
#pragma unroll
            for (int j = 0; j < 8; ++j) acc[i][j] *= sc;
        }
#pragma unroll 4
        for (int jj = 0; jj < KT; ++jj) {
            float4 v0 = *(float4*)&Vs[jj * HEADDIM + tx * 8];
            float4 v1 = *(float4*)&Vs[jj * HEADDIM + tx * 8 + 4];
#pragma unroll
            for (int i = 0; i < 4; ++i) {
                float p = Ss[(ty * 4 + i) * KT + jj];
                acc[i][0] += p * v0.x;
                acc[i][1] += p * v0.y;
                acc[i][2] += p * v0.z;
                acc[i][3] += p * v0.w;
                acc[i][4] += p * v1.x;
                acc[i][5] += p * v1.y;
                acc[i][6] += p * v1.z;
                acc[i][7] += p * v1.w;
            }
        }
    }

    float* obase = O + ((size_t)(b * SEQ + q0)) * HIDDEN + h * HEADDIM;
#pragma unroll
    for (int i = 0; i < 4; ++i) {
        int r = ty * 4 + i;
        float inv = 1.f / rowl[r];
        float4 o0 = make_float4(acc[i][0] * inv, acc[i][1] * inv,
                                acc[i][2] * inv, acc[i][3] * inv);
        float4 o1 = make_float4(acc[i][4] * inv, acc[i][5] * inv,
                                acc[i][6] * inv, acc[i][7] * inv);
        *(float4*)&obase[(size_t)r * HIDDEN + tx * 8]     = o0;
        *(float4*)&obase[(size_t)r * HIDDEN + tx * 8 + 4] = o1;
    }
}

// ---------------------------------------------------------------------------
// Launcher
// ---------------------------------------------------------------------------
extern "C" void kernel_launch(void* const* d_in, const int* in_sizes, int n_in,
                              void* d_out, int out_size)
{
    const float* x  = (const float*)d_in[0];
    const float* wq = (const float*)d_in[1];
    const float* bq = (const float*)d_in[2];
    const float* wk = (const float*)d_in[3];
    const float* bk = (const float*)d_in[4];
    const float* wv = (const float*)d_in[5];
    const float* bv = (const float*)d_in[6];
    const float* wo = (const float*)d_in[7];
    const float* bo = (const float*)d_in[8];
    float* out = (float*)d_out;

    float *Qp, *Kp, *Vp, *Op;
    cudaGetSymbolAddress((void**)&Qp, g_Q);
    cudaGetSymbolAddress((void**)&Kp, g_K);
    cudaGetSymbolAddress((void**)&Vp, g_V);
    cudaGetSymbolAddress((void**)&Op, g_O);

    cudaFuncSetAttribute(gemm_tf32_kernel,
                         cudaFuncAttributeMaxDynamicSharedMemorySize,
                         GEMM_SMEM_BYTES);
    cudaFuncSetAttribute(attn_kernel,
                         cudaFuncAttributeMaxDynamicSharedMemorySize,
                         ATTN_SMEM_BYTES);

    // Projections (tf32 tensor cores)
    {
        dim3 gq(HIDDEN / TBN, ROWS / TBM);
        gemm_tf32_kernel<<<gq, 256, GEMM_SMEM_BYTES>>>(x, wq, bq, Qp, ROWS, HIDDEN, HIDDEN);
        dim3 gk(KVDIM / TBN, ROWS / TBM);
        gemm_tf32_kernel<<<gk, 256, GEMM_SMEM_BYTES>>>(x, wk, bk, Kp, ROWS, KVDIM, HIDDEN);
        gemm_tf32_kernel<<<gk, 256, GEMM_SMEM_BYTES>>>(x, wv, bv, Vp, ROWS, KVDIM, HIDDEN);
    }

    // Attention (fp32, unchanged)
    {
        dim3 ga(SEQ / QT, NHEADS, BATCH);
        attn_kernel<<<ga, 256, ATTN_SMEM_BYTES>>>(Qp, Kp, Vp, Op);
    }

    // Output projection (tf32 tensor cores)
    {
        dim3 go(HIDDEN / TBN, ROWS / TBM);
        gemm_tf32_kernel<<<go, 256, GEMM_SMEM_BYTES>>>(Op, wo, bo, out, ROWS, HIDDEN, HIDDEN);
    }
}